// round 11
// baseline (speedup 1.0000x reference)
#include <cuda_runtime.h>
#include <cstdint>

// QuantumKANRegressor: out[b] = sum_f sum_j kan[f,j] * T_j( tanh( sum_k w[f,k]*T_{k+1}(X[b,f]) / sum_k|w[f,k]| ) )
// B=65536, F=64, DEG=16 (T_1..T_16), KAN_DEG=5 (T_0..T_5)
//
// R11 (= R10 resubmit; R10 bench died to broker infra failure):
// even/odd Chebyshev split. With y = 2x^2-1:
//   sum_k w_k T_k(x) = sum_m e_m T_m(y)  +  x * sum_m c_m T_m(y)
// (odd-order map folded into c at preprocess time). One shared deg-8
// recurrence in y, two dot accumulators. Dot coefficients = 16 packed f32x2
// values kept as NAMED scalar registers (indexed arrays get demoted to local
// memory -- measured in R1/4/5/8). Sign-folded recurrence avoids negations.

typedef unsigned long long ull;

__device__ __forceinline__ ull pk2(float lo, float hi) {
    ull d; asm("mov.b64 %0, {%1, %2};" : "=l"(d) : "f"(lo), "f"(hi)); return d;
}
__device__ __forceinline__ void upk2(ull v, float& lo, float& hi) {
    asm("mov.b64 {%0, %1}, %2;" : "=f"(lo), "=f"(hi) : "l"(v));
}
__device__ __forceinline__ ull fma2(ull a, ull b, ull c) {
    ull d; asm("fma.rn.f32x2 %0, %1, %2, %3;" : "=l"(d) : "l"(a), "l"(b), "l"(c)); return d;
}
__device__ __forceinline__ ull add2(ull a, ull b) {
    ull d; asm("add.rn.f32x2 %0, %1, %2;" : "=l"(d) : "l"(a), "l"(b)); return d;
}
__device__ __forceinline__ ull mul2(ull a, ull b) {
    ull d; asm("mul.rn.f32x2 %0, %1, %2;" : "=l"(d) : "l"(a), "l"(b)); return d;
}
__device__ __forceinline__ float ex2f(float x) {
    float y; asm("ex2.approx.f32 %0, %1;" : "=f"(y) : "f"(x)); return y;
}
__device__ __forceinline__ float rcpf(float x) {
    float y; asm("rcp.approx.f32 %0, %1;" : "=f"(y) : "f"(x)); return y;
}
// tanh(f) = 1 - 2/(1 + exp(2f)); exp via ex2 (MUFU). ~1e-6 abs error on |f|<=1.
__device__ __forceinline__ float tanh_fast(float f) {
    float e = ex2f(f * 2.8853900817779268f);   // 2 * log2(e)
    float r = rcpf(e + 1.0f);
    return fmaf(-2.0f, r, 1.0f);
}

static constexpr int F    = 64;
static constexpr int NBLK = 444;   // 3 CTAs/SM * 148 SMs
static constexpr int NTHR = 256;

__global__ void __launch_bounds__(NTHR, 3)
qkan_kernel(const float* __restrict__ X,
            const float* __restrict__ W,    // [F, 16]
            const float* __restrict__ KC,   // [1, F, 6]
            float* __restrict__ out,        // [B]
            int B)
{
    // KAN Horner coefficients in SMEM (cold: 6 LDS.64/group, conflict-free).
    __shared__ ull pc_s[6][32];

    const int tid  = threadIdx.x;
    const int lane = tid & 31;

    if (tid < 32) {
        // KAN Chebyshev (deg 5) -> monomial Horner coefficients, packed per lane.
        float pm[2][6];
        #pragma unroll
        for (int i = 0; i < 2; ++i) {
            const int f = 2 * tid + i;
            const float k0 = __ldg(KC + f*6+0), k1 = __ldg(KC + f*6+1), k2 = __ldg(KC + f*6+2);
            const float k3 = __ldg(KC + f*6+3), k4 = __ldg(KC + f*6+4), k5 = __ldg(KC + f*6+5);
            pm[i][0] = k0 - k2 + k4;
            pm[i][1] = k1 - 3.0f*k3 + 5.0f*k5;
            pm[i][2] = 2.0f*k2 - 8.0f*k4;
            pm[i][3] = 4.0f*k3 - 20.0f*k5;
            pm[i][4] = 8.0f*k4;
            pm[i][5] = 16.0f*k5;
        }
        #pragma unroll
        for (int k = 0; k < 6; ++k) pc_s[k][tid] = pk2(pm[0][k], pm[1][k]);
    }

    // ---- per-thread even/odd coefficient preprocessing (one-time) ----
    // Lane owns features f0=2*lane, f1=2*lane+1 packed (f0, f1).
    // e_m (m=1..8): even orders 2m -> w[2m-1]; c_m (m=0..7): fold of odd
    // orders via T_{2m+1}(x) = x*(2T_m(y) - 2T_{m-1}(y) + ... +- T_0(y)).
    // Sign-folded recurrence S_m: S_1=y, S_m = fma((m odd? +2y : -2y), S_{m-1}, S_{m-2});
    // S_m = s_m*T_m(y), s_m = -1 for m mod 4 in {2,3}; s folded into e,c.
    float ew[2][8], cw[2][8];
    #pragma unroll
    for (int i = 0; i < 2; ++i) {
        const int f = 2 * lane + i;
        float wv[16];
        float den = 0.0f;
        #pragma unroll
        for (int k = 0; k < 16; ++k) { wv[k] = __ldg(W + f * 16 + k); den += fabsf(wv[k]); }
        const float rd = 1.0f / den;
        #pragma unroll
        for (int m = 1; m <= 8; ++m) {
            float t = wv[2 * m - 1] * rd;      // even order 2m
            if (m & 2) t = -t;                 // fold s_m
            ew[i][m - 1] = t;
        }
        // suffix alternating sums of odd-order weights: S_m = om_m - S_{m+1}
        float s = 0.0f;
        #pragma unroll
        for (int m = 7; m >= 0; --m) {
            s = wv[2 * m] * rd - s;            // om_m = w[2m] (order 2m+1)
            cw[i][m] = s;
        }
        #pragma unroll
        for (int m = 1; m <= 7; ++m) {
            float t = 2.0f * cw[i][m];
            if (m & 2) t = -t;                 // fold s_m
            cw[i][m] = t;
        }
        // c_0 multiplies T_0 = 1 (s_0 = +1): unchanged
    }
    // Named packed registers (NOT arrays -> cannot be demoted to local).
    const ull E1 = pk2(ew[0][0], ew[1][0]);
    const ull E2 = pk2(ew[0][1], ew[1][1]);
    const ull E3 = pk2(ew[0][2], ew[1][2]);
    const ull E4 = pk2(ew[0][3], ew[1][3]);
    const ull E5 = pk2(ew[0][4], ew[1][4]);
    const ull E6 = pk2(ew[0][5], ew[1][5]);
    const ull E7 = pk2(ew[0][6], ew[1][6]);
    const ull E8 = pk2(ew[0][7], ew[1][7]);
    const ull C0 = pk2(cw[0][0], cw[1][0]);
    const ull C1 = pk2(cw[0][1], cw[1][1]);
    const ull C2 = pk2(cw[0][2], cw[1][2]);
    const ull C3 = pk2(cw[0][3], cw[1][3]);
    const ull C4 = pk2(cw[0][4], cw[1][4]);
    const ull C5 = pk2(cw[0][5], cw[1][5]);
    const ull C6 = pk2(cw[0][6], cw[1][6]);
    const ull C7 = pk2(cw[0][7], cw[1][7]);
    __syncthreads();

    const ull ONE2 = 0x3F8000003F800000ull;   // (1.0f, 1.0f)
    const ull NEG1 = 0xBF800000BF800000ull;   // (-1.0f, -1.0f)
    const ull NEG2 = 0xC0000000C0000000ull;   // (-2.0f, -2.0f)

    const int gw = (blockIdx.x * NTHR + tid) >> 5;
    const int nW = (gridDim.x * NTHR) >> 5;
    const int nG = B / 2;

    int g = gw;
    float2 cx0, cx1;
    if (g < nG) {
        const float2* base = (const float2*)X + (size_t)(2 * g) * 32 + lane;
        cx0 = __ldg(base);
        cx1 = __ldg(base + 32);
    }

    while (g < nG) {
        const int gn = g + nW;
        float2 nx0, nx1;
        if (gn < nG) {
            const float2* base = (const float2*)X + (size_t)(2 * gn) * 32 + lane;
            nx0 = __ldg(base);
            nx1 = __ldg(base + 32);
        }

        // ---- two independent row chains ----
        const ull x0 = pk2(cx0.x, cx0.y);
        const ull x1 = pk2(cx1.x, cx1.y);
        const ull d0 = add2(x0, x0), d1 = add2(x1, x1);
        const ull y0 = fma2(d0, x0, NEG1);         // y = 2x^2 - 1
        const ull y1 = fma2(d1, x1, NEG1);
        const ull p0 = add2(y0, y0), p1 = add2(y1, y1);   // +2y
        const ull m0 = mul2(y0, NEG2), m1 = mul2(y1, NEG2); // -2y
        ull aE0 = mul2(E1, y0),        aE1 = mul2(E1, y1);
        ull aO0 = fma2(C1, y0, C0),    aO1 = fma2(C1, y1, C0);
        ull sA0 = ONE2, sB0 = y0,      sA1 = ONE2, sB1 = y1;
        // m=2 (-2y)
        { ull n0 = fma2(m0, sB0, sA0), n1 = fma2(m1, sB1, sA1);
          aE0 = fma2(E2, n0, aE0); aE1 = fma2(E2, n1, aE1);
          aO0 = fma2(C2, n0, aO0); aO1 = fma2(C2, n1, aO1);
          sA0 = sB0; sB0 = n0; sA1 = sB1; sB1 = n1; }
        // m=3 (+2y)
        { ull n0 = fma2(p0, sB0, sA0), n1 = fma2(p1, sB1, sA1);
          aE0 = fma2(E3, n0, aE0); aE1 = fma2(E3, n1, aE1);
          aO0 = fma2(C3, n0, aO0); aO1 = fma2(C3, n1, aO1);
          sA0 = sB0; sB0 = n0; sA1 = sB1; sB1 = n1; }
        // m=4 (-2y)
        { ull n0 = fma2(m0, sB0, sA0), n1 = fma2(m1, sB1, sA1);
          aE0 = fma2(E4, n0, aE0); aE1 = fma2(E4, n1, aE1);
          aO0 = fma2(C4, n0, aO0); aO1 = fma2(C4, n1, aO1);
          sA0 = sB0; sB0 = n0; sA1 = sB1; sB1 = n1; }
        // m=5 (+2y)
        { ull n0 = fma2(p0, sB0, sA0), n1 = fma2(p1, sB1, sA1);
          aE0 = fma2(E5, n0, aE0); aE1 = fma2(E5, n1, aE1);
          aO0 = fma2(C5, n0, aO0); aO1 = fma2(C5, n1, aO1);
          sA0 = sB0; sB0 = n0; sA1 = sB1; sB1 = n1; }
        // m=6 (-2y)
        { ull n0 = fma2(m0, sB0, sA0), n1 = fma2(m1, sB1, sA1);
          aE0 = fma2(E6, n0, aE0); aE1 = fma2(E6, n1, aE1);
          aO0 = fma2(C6, n0, aO0); aO1 = fma2(C6, n1, aO1);
          sA0 = sB0; sB0 = n0; sA1 = sB1; sB1 = n1; }
        // m=7 (+2y)
        { ull n0 = fma2(p0, sB0, sA0), n1 = fma2(p1, sB1, sA1);
          aE0 = fma2(E7, n0, aE0); aE1 = fma2(E7, n1, aE1);
          aO0 = fma2(C7, n0, aO0); aO1 = fma2(C7, n1, aO1);
          sA0 = sB0; sB0 = n0; sA1 = sB1; sB1 = n1; }
        // m=8 (-2y), E only
        { ull n0 = fma2(m0, sB0, sA0), n1 = fma2(m1, sB1, sA1);
          aE0 = fma2(E8, n0, aE0); aE1 = fma2(E8, n1, aE1); }

        const ull f0 = fma2(x0, aO0, aE0);         // feat = E + x*O
        const ull f1 = fma2(x1, aO1, aE1);

        // tanh (MUFU) then deg-5 Horner (coeffs from SMEM, conflict-free)
        float a0, b0, a1, b1;
        upk2(f0, a0, b0); upk2(f1, a1, b1);
        const ull z0 = pk2(tanh_fast(a0), tanh_fast(b0));
        const ull z1 = pk2(tanh_fast(a1), tanh_fast(b1));
        const ull q5 = pc_s[5][lane], q4 = pc_s[4][lane], q3 = pc_s[3][lane];
        const ull q2 = pc_s[2][lane], q1 = pc_s[1][lane], q0 = pc_s[0][lane];
        ull t0 = fma2(q5, z0, q4);
        ull t1 = fma2(q5, z1, q4);
        t0 = fma2(t0, z0, q3); t1 = fma2(t1, z1, q3);
        t0 = fma2(t0, z0, q2); t1 = fma2(t1, z1, q2);
        t0 = fma2(t0, z0, q1); t1 = fma2(t1, z1, q1);
        t0 = fma2(t0, z0, q0); t1 = fma2(t1, z1, q0);
        float s0lo, s0hi, s1lo, s1hi;
        upk2(t0, s0lo, s0hi); upk2(t1, s1lo, s1hi);
        const float s0 = s0lo + s0hi;
        const float s1 = s1lo + s1hi;

        // ---- warp reduction: pack (row0,row1), 5-level 64-bit tree ----
        {
            ull m = pk2(s0, s1);
            #pragma unroll
            for (int off = 16; off; off >>= 1)
                m = add2(m, __shfl_xor_sync(0xffffffffu, m, off));
            if (lane == 0) {
                float lo, hi; upk2(m, lo, hi);
                ((float2*)out)[g] = make_float2(lo, hi);
            }
        }

        cx0 = nx0; cx1 = nx1;
        g = gn;
    }
}

extern "C" void kernel_launch(void* const* d_in, const int* in_sizes, int n_in,
                              void* d_out, int out_size)
{
    const float* X  = (const float*)d_in[0];   // [B, 64] fp32
    const float* W  = (const float*)d_in[1];   // [64, 16] fp32
    const float* KC = (const float*)d_in[2];   // [1, 64, 6] fp32
    float* out = (float*)d_out;                // [B] fp32

    const int B = in_sizes[0] / F;             // 65536

    qkan_kernel<<<NBLK, NTHR>>>(X, W, KC, out, B);
}

// round 12
// speedup vs baseline: 1.6335x; 1.6335x over previous
#include <cuda_runtime.h>
#include <cstdint>

// QuantumKANRegressor: out[b] = sum_f sum_j kan[f,j] * T_j( tanh( sum_k w[f,k]*T_{k+1}(X[b,f]) / sum_k|w[f,k]| ) )
// B=65536, F=64, DEG=16 (T_1..T_16), KAN_DEG=5 (T_0..T_5)
//
// R12: even/odd Chebyshev split (validated correct in R11) with coefficients
// in SMEM planes (the only storage scheme that never spilled: R3/R9).
//   y = 2x^2-1:  sum_k w_k T_k(x) = sum_m e_m T_m(y) + x * sum_m c_m T_m(y)
// One deg-8 recurrence in y per chain, two dot accumulators. (E_m, C_m)
// packed as ulonglong2 -> LDS.128. R=4 rows/group amortizes LDS bytes;
// 4 independent chains for ILP; 3 CTAs/SM; register demand ~76 < 85 cap.

typedef unsigned long long ull;

__device__ __forceinline__ ull pk2(float lo, float hi) {
    ull d; asm("mov.b64 %0, {%1, %2};" : "=l"(d) : "f"(lo), "f"(hi)); return d;
}
__device__ __forceinline__ void upk2(ull v, float& lo, float& hi) {
    asm("mov.b64 {%0, %1}, %2;" : "=f"(lo), "=f"(hi) : "l"(v));
}
__device__ __forceinline__ ull fma2(ull a, ull b, ull c) {
    ull d; asm("fma.rn.f32x2 %0, %1, %2, %3;" : "=l"(d) : "l"(a), "l"(b), "l"(c)); return d;
}
__device__ __forceinline__ ull add2(ull a, ull b) {
    ull d; asm("add.rn.f32x2 %0, %1, %2;" : "=l"(d) : "l"(a), "l"(b)); return d;
}
__device__ __forceinline__ ull mul2(ull a, ull b) {
    ull d; asm("mul.rn.f32x2 %0, %1, %2;" : "=l"(d) : "l"(a), "l"(b)); return d;
}
__device__ __forceinline__ float ex2f(float x) {
    float y; asm("ex2.approx.f32 %0, %1;" : "=f"(y) : "f"(x)); return y;
}
__device__ __forceinline__ float rcpf(float x) {
    float y; asm("rcp.approx.f32 %0, %1;" : "=f"(y) : "f"(x)); return y;
}
// tanh(f) = 1 - 2/(1 + exp(2f)); exp via ex2 (MUFU). ~1e-6 abs error on |f|<=1.
__device__ __forceinline__ float tanh_fast(float f) {
    float e = ex2f(f * 2.8853900817779268f);   // 2 * log2(e)
    float r = rcpf(e + 1.0f);
    return fmaf(-2.0f, r, 1.0f);
}

static constexpr int F    = 64;
static constexpr int NBLK = 444;   // 3 CTAs/SM * 148 SMs
static constexpr int NTHR = 256;
static constexpr int R    = 4;     // rows per warp-iteration

__global__ void __launch_bounds__(NTHR, 3)
qkan_kernel(const float* __restrict__ X,
            const float* __restrict__ W,    // [F, 16]
            const float* __restrict__ KC,   // [1, F, 6]
            float* __restrict__ out,        // [B]
            int B)
{
    // SMEM planes, lane-indexed, packed (f0=2*lane, f1=2*lane+1):
    //   ec_s[m-1][lane] = (E_m, C_m) for m=1..8 (C_8 = 0)  -> LDS.128
    //   c0_s[lane]      = C_0                               -> LDS.64
    //   pc_s[k][lane]   = KAN Horner coefficients           -> LDS.64
    __shared__ ulonglong2 ec_s[8][32];
    __shared__ ull c0_s[32];
    __shared__ ull pc_s[6][32];

    const int tid  = threadIdx.x;
    const int lane = tid & 31;

    if (tid < 32) {
        // ---- even/odd coefficient preprocessing (identical math to R11) ----
        // e_m (m=1..8): even orders 2m -> w[2m-1]; c_m: fold of odd orders via
        // T_{2m+1}(x) = x*(2T_m(y) - 2T_{m-1}(y) + ... +- T_0(y)).
        // Sign-folded recurrence S_m = s_m*T_m(y), s_m = -1 for m mod 4 in {2,3};
        // s folded into e, c.
        float ew[2][8], cw[2][8];
        #pragma unroll
        for (int i = 0; i < 2; ++i) {
            const int f = 2 * tid + i;
            float wv[16];
            float den = 0.0f;
            #pragma unroll
            for (int k = 0; k < 16; ++k) { wv[k] = __ldg(W + f * 16 + k); den += fabsf(wv[k]); }
            const float rd = 1.0f / den;
            #pragma unroll
            for (int m = 1; m <= 8; ++m) {
                float t = wv[2 * m - 1] * rd;      // even order 2m
                if (m & 2) t = -t;                 // fold s_m
                ew[i][m - 1] = t;
            }
            float s = 0.0f;
            #pragma unroll
            for (int m = 7; m >= 0; --m) {
                s = wv[2 * m] * rd - s;            // odd order 2m+1 suffix fold
                cw[i][m] = s;
            }
            #pragma unroll
            for (int m = 1; m <= 7; ++m) {
                float t = 2.0f * cw[i][m];
                if (m & 2) t = -t;                 // fold s_m
                cw[i][m] = t;
            }
        }
        #pragma unroll
        for (int m = 1; m <= 7; ++m)
            ec_s[m - 1][tid] = make_ulonglong2(pk2(ew[0][m - 1], ew[1][m - 1]),
                                               pk2(cw[0][m],     cw[1][m]));
        ec_s[7][tid] = make_ulonglong2(pk2(ew[0][7], ew[1][7]), 0ull);
        c0_s[tid]    = pk2(cw[0][0], cw[1][0]);

        // ---- KAN Chebyshev (deg 5) -> monomial Horner coefficients ----
        float pm[2][6];
        #pragma unroll
        for (int i = 0; i < 2; ++i) {
            const int f = 2 * tid + i;
            const float k0 = __ldg(KC + f*6+0), k1 = __ldg(KC + f*6+1), k2 = __ldg(KC + f*6+2);
            const float k3 = __ldg(KC + f*6+3), k4 = __ldg(KC + f*6+4), k5 = __ldg(KC + f*6+5);
            pm[i][0] = k0 - k2 + k4;
            pm[i][1] = k1 - 3.0f*k3 + 5.0f*k5;
            pm[i][2] = 2.0f*k2 - 8.0f*k4;
            pm[i][3] = 4.0f*k3 - 20.0f*k5;
            pm[i][4] = 8.0f*k4;
            pm[i][5] = 16.0f*k5;
        }
        #pragma unroll
        for (int k = 0; k < 6; ++k) pc_s[k][tid] = pk2(pm[0][k], pm[1][k]);
    }
    __syncthreads();

    const ull ONE2 = 0x3F8000003F800000ull;   // (1.0f, 1.0f)
    const ull NEG1 = 0xBF800000BF800000ull;   // (-1.0f, -1.0f)
    const ull NEG2 = 0xC0000000C0000000ull;   // (-2.0f, -2.0f)

    const int gw = (blockIdx.x * NTHR + tid) >> 5;
    const int nW = (gridDim.x * NTHR) >> 5;
    const int nG = B / R;                      // B % 4 == 0

    // X rows are 64 floats = 32 ulls; lane's packed feature pair is ull #lane.
    const ull* Xq = (const ull*)X;

    int g = gw;
    ull x[R];
    if (g < nG) {
        const ull* base = Xq + (size_t)(R * g) * 32 + lane;
        #pragma unroll
        for (int r = 0; r < R; ++r) x[r] = __ldg(base + r * 32);
    }

    while (g < nG) {
        const int gn = g + nW;
        ull nx[R];
        if (gn < nG) {
            const ull* base = Xq + (size_t)(R * gn) * 32 + lane;
            #pragma unroll
            for (int r = 0; r < R; ++r) nx[r] = __ldg(base + r * 32);
        }

        // ---- 4 independent chains, deg-8 recurrence in y ----
        ull y[R], p[R], m_[R], sA[R], sB[R], aE[R], aO[R];
        {
            const ull c0 = c0_s[lane];
            const ulonglong2 ec1 = ec_s[0][lane];
            #pragma unroll
            for (int r = 0; r < R; ++r) {
                y[r]  = fma2(add2(x[r], x[r]), x[r], NEG1);   // y = 2x^2 - 1
                p[r]  = add2(y[r], y[r]);                     // +2y
                m_[r] = mul2(y[r], NEG2);                     // -2y
                sA[r] = ONE2;
                sB[r] = y[r];
                aE[r] = mul2(ec1.x, y[r]);                    // E_1 * S_1
                aO[r] = fma2(ec1.y, y[r], c0);                // C_1 * S_1 + C_0
            }
        }
        #pragma unroll
        for (int mm = 2; mm <= 7; ++mm) {
            const ulonglong2 ec = ec_s[mm - 1][lane];
            #pragma unroll
            for (int r = 0; r < R; ++r) {
                const ull n = fma2((mm & 1) ? p[r] : m_[r], sB[r], sA[r]);
                aE[r] = fma2(ec.x, n, aE[r]);
                aO[r] = fma2(ec.y, n, aO[r]);
                sA[r] = sB[r]; sB[r] = n;
            }
        }
        {   // m = 8: even only
            const ulonglong2 ec = ec_s[7][lane];
            #pragma unroll
            for (int r = 0; r < R; ++r) {
                const ull n = fma2(m_[r], sB[r], sA[r]);
                aE[r] = fma2(ec.x, n, aE[r]);
            }
        }

        // feat = E + x*O; tanh (MUFU); deg-5 Horner (SMEM coeffs)
        ull z[R];
        #pragma unroll
        for (int r = 0; r < R; ++r) {
            const ull f = fma2(x[r], aO[r], aE[r]);
            float lo, hi; upk2(f, lo, hi);
            z[r] = pk2(tanh_fast(lo), tanh_fast(hi));
        }
        const ull q5 = pc_s[5][lane], q4 = pc_s[4][lane], q3 = pc_s[3][lane];
        const ull q2 = pc_s[2][lane], q1 = pc_s[1][lane], q0 = pc_s[0][lane];
        float s[R];
        #pragma unroll
        for (int r = 0; r < R; ++r) {
            ull t = fma2(q5, z[r], q4);
            t = fma2(t, z[r], q3);
            t = fma2(t, z[r], q2);
            t = fma2(t, z[r], q1);
            t = fma2(t, z[r], q0);
            float lo, hi; upk2(t, lo, hi);
            s[r] = lo + hi;
        }

        // ---- folded warp reduction: 4 rows -> 2 packed values, 5 levels ----
        {
            const ull A  = pk2(s[0], s[1]);              // rows Rg, Rg+1
            const ull Bp = pk2(s[2], s[3]);              // rows Rg+2, Rg+3
            ull acc = (lane & 16) ? Bp : A;
            ull oth = (lane & 16) ? A  : Bp;
            acc = add2(acc, __shfl_xor_sync(0xffffffffu, oth, 16));
            #pragma unroll
            for (int off = 8; off; off >>= 1)
                acc = add2(acc, __shfl_xor_sync(0xffffffffu, acc, off));
            if ((lane & 15) == 0) {
                // lane 0 -> rows (Rg, Rg+1); lane 16 -> rows (Rg+2, Rg+3)
                ((ull*)out)[2 * g + (lane >> 4)] = acc;
            }
        }

        #pragma unroll
        for (int r = 0; r < R; ++r) x[r] = nx[r];
        g = gn;
    }
}

extern "C" void kernel_launch(void* const* d_in, const int* in_sizes, int n_in,
                              void* d_out, int out_size)
{
    const float* X  = (const float*)d_in[0];   // [B, 64] fp32
    const float* W  = (const float*)d_in[1];   // [64, 16] fp32
    const float* KC = (const float*)d_in[2];   // [1, 64, 6] fp32
    float* out = (float*)d_out;                // [B] fp32

    const int B = in_sizes[0] / F;             // 65536

    qkan_kernel<<<NBLK, NTHR>>>(X, W, KC, out, B);
}